// round 14
// baseline (speedup 1.0000x reference)
#include <cuda_runtime.h>
#include <math.h>

// Problem constants
#define B_    64
#define T_    1024
#define DIN_  512
#define H_    2048
#define DOUT_ 512
#define FH_   8192     // 4*H
#define NCTA  128
#define NTHR  512

typedef unsigned long long u64;

// ---------------- static device scratch (no allocation allowed) ----------------
__device__ float g_h[2][B_ * H_];            // ping-pong hidden state
__device__ float g_y[B_ * DOUT_];            // previous prediction y_{t-1}
__device__ float g_ypart[16][B_ * DOUT_];    // split-K partials for y projection
__device__ unsigned g_bar_count = 0;         // grid barrier arrival counter
__device__ volatile unsigned g_bar_gen = 0;  // grid barrier generation (monotonic)

// ---------------- packed f32x2 helpers (ptxas will not auto-fuse) --------------
__device__ __forceinline__ u64 ffma2(u64 a, u64 b, u64 c) {
    u64 d;
    asm("fma.rn.f32x2 %0, %1, %2, %3;" : "=l"(d) : "l"(a), "l"(b), "l"(c));
    return d;
}
__device__ __forceinline__ u64 dup2(float x) {
    u64 d;
    asm("mov.b64 %0, {%1, %1};" : "=l"(d) : "f"(x));
    return d;
}
__device__ __forceinline__ float sgm(float v) { return 1.0f / (1.0f + expf(-v)); }

// ---------------- software grid barrier (all 128 CTAs resident) ----------------
__device__ __forceinline__ void gridbar(unsigned target) {
    __syncthreads();
    if (threadIdx.x == 0) {
        __threadfence();
        if (atomicAdd(&g_bar_count, 1u) == NCTA - 1u) {
            g_bar_count = 0u;
            __threadfence();
            g_bar_gen = target;
        } else {
            while ((int)(g_bar_gen - target) < 0) { }
        }
        __threadfence();
    }
    __syncthreads();
}

// ---------------- gate GEMM operand source per K-chunk ----------------
// kg in [0,3072): [0,512)=x_t (Wi rows), [512,1024)=y_prev (Wi rows),
// [1024,3072)=h_prev (Wh rows). Chunk width 32 divides all boundaries.
__device__ __forceinline__ void chunk_src(
    int k0, int t, const float* __restrict__ x, const float* __restrict__ Wi,
    const float* __restrict__ Wh, const float* __restrict__ yprev,
    const float* __restrict__ hprev,
    const float*& Ab, size_t& strA, const float*& Wb)
{
    if (k0 < 512) {
        Ab = x + (size_t)t * DIN_ + (size_t)k0;   // x[m][t][k], row stride T*DIN
        strA = (size_t)T_ * DIN_;
        Wb = Wi + (size_t)k0 * FH_;
    } else if (k0 < 1024) {
        Ab = yprev + (k0 - 512);
        strA = DOUT_;
        Wb = Wi + (size_t)k0 * FH_;
    } else {
        Ab = hprev + (k0 - 1024);
        strA = H_;
        Wb = Wh + (size_t)(k0 - 1024) * FH_;
    }
}

// ---------------- dynamic smem layout (floats) ----------------
// Gates GEMM:
//   Asd(g,buf): dup-packed A, 32 rows x 132 floats (row kk = 64 m dup-pairs)
//   B planes(g,buf,pl): 32 rows x 36 floats each; plane pl holds 16B unit
//     [cols q*8+4*pl .. +3] at [kk][q*4] -> LDS.128 hits 8 distinct 16B banks.
//   z staging aliases the A buffers after the GEMM's final syncthreads.
#define AOFF(g, b)  ((g) * 8448 + (b) * 4224)
#define BOFF(g, b)  (16896 + (g) * 4608 + (b) * 2304)
#define SMEM_FLOATS 26112
#define SMEM_BYTES  (SMEM_FLOATS * 4)

// ======================= single persistent kernel =======================
// 128 CTAs x 512 threads. CTA bx owns hidden units u0=16*bx..u0+15 for all 64
// batch rows: its 64x64 z tile columns are [i|f|g|o] x 16 units (smem col j ->
// weight column (j>>4)*2048 + u0 + (j&15)). Two in-CTA K-groups (warps 0-7:
// K[0,1536); warps 8-15: K[1536,3072)) each run a 2m x 8n per-thread tile and
// their partial z tiles are summed in the fused LSTM epilogue.
__global__ void __launch_bounds__(NTHR, 1) k_lstm_persistent(
    const float* __restrict__ x,  const float* __restrict__ c0,
    const float* __restrict__ h0, const float* __restrict__ y0,
    const float* __restrict__ Wi, const float* __restrict__ Wh,
    const float* __restrict__ bias, const float* __restrict__ Wo,
    const float* __restrict__ bo,
    float* __restrict__ out_c, float* __restrict__ out_h,
    float* __restrict__ out_y, float* __restrict__ out_ys)
{
    extern __shared__ __align__(16) float smB[];

    const int tid = threadIdx.x;
    const int bx  = blockIdx.x;
    const int u0  = bx * 16;

    // ----- gates GEMM mappings (per K-group) -----
    const int g   = tid >> 8;          // K-group 0/1
    const int gt  = tid & 255;
    const int gtx = gt & 7;            // n0 = gtx*8
    const int gty = gt >> 3;           // m0 = gty*2  (32 values)
    const int n0  = gtx * 8;
    // A loader: row am, k-offset ak (two float4s at ak, ak+4)
    const int am = gt & 63;
    const int ak = (gt >> 6) * 8;      // 0,8,16,24
    // B loader: row bk (0..31), column group bq (cols bq*8..bq*8+7)
    const int bk = gt >> 3;
    const int bq = gt & 7;
    const int j0 = bq * 8;
    const int gcol0 = ((j0 >> 4) * 2048) + u0 + (j0 & 15);  // gate-interleaved

    unsigned bar = g_bar_gen;   // persisted base generation (no writers yet)

    // ---------------- init: states ----------------
    {
#pragma unroll
        for (int r = 0; r < 2; r++) {
            int cell = tid + NTHR * r;            // 0..1023
            int mm = cell >> 4, up = cell & 15;
            size_t gi = (size_t)mm * H_ + u0 + up;
            out_c[gi]  = c0[gi];
            g_h[0][gi] = h0[gi];
        }
        if (tid < 256) { int yi = bx * 256 + tid; g_y[yi] = y0[yi]; }
    }
    gridbar(++bar);

    // ---------------- time loop ----------------
    for (int t = 0; t < T_; t++) {
        const int pp = t & 1;
        const float* __restrict__ yprev = g_y;
        const float* __restrict__ hprev = g_h[pp];
        float* __restrict__ hnext       = g_h[pp ^ 1];

        // ===== gates GEMM: per group 48 chunks of K=32, double-buffered =====
        u64 acc[8];
#pragma unroll
        for (int i = 0; i < 8; i++) acc[i] = 0ull;

        {   // preload chunk 0 into buffer 0
            const float *Ab, *Wb; size_t strA;
            chunk_src(g * 1536, t, x, Wi, Wh, yprev, hprev, Ab, strA, Wb);
            float4 a40 = __ldcg((const float4*)(Ab + (size_t)am * strA + ak));
            float4 a41 = __ldcg((const float4*)(Ab + (size_t)am * strA + ak + 4));
            float4 b40 = __ldcg((const float4*)(Wb + (size_t)bk * FH_ + gcol0));
            float4 b41 = __ldcg((const float4*)(Wb + (size_t)bk * FH_ + gcol0 + 4));
            float* Ad = smB + AOFF(g, 0);
            *(float2*)&Ad[(ak + 0) * 132 + am * 2] = make_float2(a40.x, a40.x);
            *(float2*)&Ad[(ak + 1) * 132 + am * 2] = make_float2(a40.y, a40.y);
            *(float2*)&Ad[(ak + 2) * 132 + am * 2] = make_float2(a40.z, a40.z);
            *(float2*)&Ad[(ak + 3) * 132 + am * 2] = make_float2(a40.w, a40.w);
            *(float2*)&Ad[(ak + 4) * 132 + am * 2] = make_float2(a41.x, a41.x);
            *(float2*)&Ad[(ak + 5) * 132 + am * 2] = make_float2(a41.y, a41.y);
            *(float2*)&Ad[(ak + 6) * 132 + am * 2] = make_float2(a41.z, a41.z);
            *(float2*)&Ad[(ak + 7) * 132 + am * 2] = make_float2(a41.w, a41.w);
            float* B0 = smB + BOFF(g, 0);
            *(float4*)&B0[bk * 36 + bq * 4]        = b40;
            *(float4*)&B0[1152 + bk * 36 + bq * 4] = b41;
        }
        __syncthreads();

        for (int c = 0; c < 48; c++) {
            const int cur = c & 1;
            const bool hn = (c + 1 < 48);
            float4 a40, a41, b40, b41;
            if (hn) {
                const float *Ab, *Wb; size_t strA;
                chunk_src(g * 1536 + (c + 1) * 32, t, x, Wi, Wh, yprev, hprev,
                          Ab, strA, Wb);
                a40 = __ldcg((const float4*)(Ab + (size_t)am * strA + ak));
                a41 = __ldcg((const float4*)(Ab + (size_t)am * strA + ak + 4));
                b40 = __ldcg((const float4*)(Wb + (size_t)bk * FH_ + gcol0));
                b41 = __ldcg((const float4*)(Wb + (size_t)bk * FH_ + gcol0 + 4));
            }

            const float* Ad = smB + AOFF(g, cur);
            const float* B0 = smB + BOFF(g, cur);
            const float* B1 = B0 + 1152;
#pragma unroll 16
            for (int kk = 0; kk < 32; kk++) {
                ulonglong2 aa = *(const ulonglong2*)&Ad[kk * 132 + gty * 4]; // {dup m0, dup m0+1}
                ulonglong2 bA = *(const ulonglong2*)&B0[kk * 36 + gtx * 4];  // pairs n0..n0+3
                ulonglong2 bB = *(const ulonglong2*)&B1[kk * 36 + gtx * 4];  // pairs n0+4..n0+7
                acc[0] = ffma2(aa.x, bA.x, acc[0]);
                acc[1] = ffma2(aa.x, bA.y, acc[1]);
                acc[2] = ffma2(aa.x, bB.x, acc[2]);
                acc[3] = ffma2(aa.x, bB.y, acc[3]);
                acc[4] = ffma2(aa.y, bA.x, acc[4]);
                acc[5] = ffma2(aa.y, bA.y, acc[5]);
                acc[6] = ffma2(aa.y, bB.x, acc[6]);
                acc[7] = ffma2(aa.y, bB.y, acc[7]);
            }

            if (hn) {
                const int nb2 = cur ^ 1;
                float* Ad2 = smB + AOFF(g, nb2);
                *(float2*)&Ad2[(ak + 0) * 132 + am * 2] = make_float2(a40.x, a40.x);
                *(float2*)&Ad2[(ak + 1) * 132 + am * 2] = make_float2(a40.y, a40.y);
                *(float2*)&Ad2[(ak + 2) * 132 + am * 2] = make_float2(a40.z, a40.z);
                *(float2*)&Ad2[(ak + 3) * 132 + am * 2] = make_float2(a40.w, a40.w);
                *(float2*)&Ad2[(ak + 4) * 132 + am * 2] = make_float2(a41.x, a41.x);
                *(float2*)&Ad2[(ak + 5) * 132 + am * 2] = make_float2(a41.y, a41.y);
                *(float2*)&Ad2[(ak + 6) * 132 + am * 2] = make_float2(a41.z, a41.z);
                *(float2*)&Ad2[(ak + 7) * 132 + am * 2] = make_float2(a41.w, a41.w);
                float* B0w = smB + BOFF(g, nb2);
                *(float4*)&B0w[bk * 36 + bq * 4]        = b40;
                *(float4*)&B0w[1152 + bk * 36 + bq * 4] = b41;
            }
            __syncthreads();
        }

        // ===== stage both groups' z partials; fused LSTM pointwise =====
        {
            float* zz = smB + g * 4352;   // z_g[m][68], aliases A buffers (post-sync)
            const int m0 = gty * 2;
            *(u64*)&zz[(m0 + 0) * 68 + n0]     = acc[0];
            *(u64*)&zz[(m0 + 0) * 68 + n0 + 2] = acc[1];
            *(u64*)&zz[(m0 + 0) * 68 + n0 + 4] = acc[2];
            *(u64*)&zz[(m0 + 0) * 68 + n0 + 6] = acc[3];
            *(u64*)&zz[(m0 + 1) * 68 + n0]     = acc[4];
            *(u64*)&zz[(m0 + 1) * 68 + n0 + 2] = acc[5];
            *(u64*)&zz[(m0 + 1) * 68 + n0 + 4] = acc[6];
            *(u64*)&zz[(m0 + 1) * 68 + n0 + 6] = acc[7];
            __syncthreads();
#pragma unroll
            for (int r = 0; r < 2; r++) {
                int cell = tid + NTHR * r;        // 0..1023
                int mm = cell >> 4, up = cell & 15;
                float zi = smB[mm * 68 + up]        + smB[4352 + mm * 68 + up]
                         + bias[u0 + up];
                float zf = smB[mm * 68 + 16 + up]   + smB[4352 + mm * 68 + 16 + up]
                         + bias[2048 + u0 + up];
                float zg = smB[mm * 68 + 32 + up]   + smB[4352 + mm * 68 + 32 + up]
                         + bias[4096 + u0 + up];
                float zo = smB[mm * 68 + 48 + up]   + smB[4352 + mm * 68 + 48 + up]
                         + bias[6144 + u0 + up];
                size_t gi = (size_t)mm * H_ + u0 + up;
                float cold = out_c[gi];            // CTA-private: L1-resident
                float nc = sgm(zf) * cold + sgm(zi) * tanhf(zg);
                float nh = sgm(zo) * tanhf(nc);
                out_c[gi] = nc;
                hnext[gi] = nh;
            }
        }
        gridbar(++bar);   // h_t published

        // ===== y projection: split K(16 x 128) x N(8 x 64) =====
        {
            const int nb = bx & 7, ks = bx >> 3;
            const int kbase = ks * 128;
            const float* __restrict__ h = g_h[pp ^ 1];
            const int ytx = tid & 15, yty = tid >> 4;      // n=ytx*4, m=yty*2
            const int yam = tid & 63, yak = (tid >> 6) * 4;
            const int ybk = tid >> 4, ybc = (tid & 15) * 4;
            u64 ya[4] = {0ull, 0ull, 0ull, 0ull};
            for (int c = 0; c < 4; c++) {
                int k0 = kbase + c * 32;
                float4 a4 = __ldcg((const float4*)(h + (size_t)yam * H_ + k0 + yak));
                float4 b4 = __ldcg((const float4*)(Wo + (size_t)(k0 + ybk) * DOUT_ + nb * 64 + ybc));
                __syncthreads();
                smB[(yak + 0) * 68 + yam] = a4.x;
                smB[(yak + 1) * 68 + yam] = a4.y;
                smB[(yak + 2) * 68 + yam] = a4.z;
                smB[(yak + 3) * 68 + yam] = a4.w;
                *(float4*)&smB[4352 + ybk * 68 + ybc] = b4;
                __syncthreads();
#pragma unroll 16
                for (int kk = 0; kk < 32; kk++) {
                    float2 av = *(const float2*)&smB[kk * 68 + yty * 2];
                    ulonglong2 bv = *(const ulonglong2*)&smB[4352 + kk * 68 + ytx * 4];
                    u64 a0 = dup2(av.x), a1 = dup2(av.y);
                    ya[0] = ffma2(a0, bv.x, ya[0]);
                    ya[1] = ffma2(a0, bv.y, ya[1]);
                    ya[2] = ffma2(a1, bv.x, ya[2]);
                    ya[3] = ffma2(a1, bv.y, ya[3]);
                }
            }
            float* d0 = &g_ypart[ks][(size_t)(yty * 2 + 0) * DOUT_ + nb * 64 + ytx * 4];
            float* d1 = &g_ypart[ks][(size_t)(yty * 2 + 1) * DOUT_ + nb * 64 + ytx * 4];
            *(u64*)d0 = ya[0]; *(u64*)(d0 + 2) = ya[1];
            *(u64*)d1 = ya[2]; *(u64*)(d1 + 2) = ya[3];
        }
        gridbar(++bar);   // partials published

        // ===== y reduce: 256 outputs per CTA =====
        if (tid < 256) {
            int o = bx * 256 + tid;               // 0..32767
            float s = __ldg(&bo[o & 511]);
#pragma unroll
            for (int ks = 0; ks < 16; ks++) s += __ldcg(&g_ypart[ks][o]);
            g_y[o] = s;
            int mm = o >> 9, cN = o & 511;
            out_ys[(size_t)mm * ((size_t)T_ * DOUT_) + (size_t)t * DOUT_ + cN] = s;
        }
        gridbar(++bar);   // y_t published
    }

    // ---------------- final: h_f, y_f ----------------
    {
        int idx = bx * NTHR + tid;                // 0..65535
        out_h[idx]         = __ldcg(&g_h[0][idx]);   // T even -> final h in buf 0
        out_h[idx + 65536] = __ldcg(&g_h[0][idx + 65536]);
        if (idx < B_ * DOUT_) out_y[idx] = __ldcg(&g_y[idx]);
    }
}

// ---------------- host launcher: ONE graph node ----------------
extern "C" void kernel_launch(void* const* d_in, const int* in_sizes, int n_in,
                              void* d_out, int out_size) {
    (void)in_sizes; (void)n_in; (void)out_size;
    const float* x  = (const float*)d_in[0];
    const float* c0 = (const float*)d_in[1];
    const float* h0 = (const float*)d_in[2];
    const float* y0 = (const float*)d_in[3];
    const float* Wi = (const float*)d_in[4];
    const float* Wh = (const float*)d_in[5];
    const float* b  = (const float*)d_in[6];
    const float* Wo = (const float*)d_in[7];
    const float* bo = (const float*)d_in[8];

    // Output layout: c_f [64,2048] | h_f [64,2048] | y_f [64,512] | ys [64,1024,512]
    float* out    = (float*)d_out;
    float* out_c  = out;
    float* out_h  = out + 131072;
    float* out_y  = out + 262144;
    float* out_ys = out + 294912;

    cudaFuncSetAttribute(k_lstm_persistent,
                         cudaFuncAttributeMaxDynamicSharedMemorySize, SMEM_BYTES);
    k_lstm_persistent<<<NCTA, NTHR, SMEM_BYTES>>>(x, c0, h0, y0, Wi, Wh, b, Wo, bo,
                                                  out_c, out_h, out_y, out_ys);
}

// round 15
// speedup vs baseline: 1.0038x; 1.0038x over previous
#include <cuda_runtime.h>
#include <math.h>

// Problem constants
#define B_    64
#define T_    1024
#define DIN_  512
#define H_    2048
#define DOUT_ 512
#define FH_   8192     // 4*H
#define NCTA  128
#define NTHR  512

typedef unsigned long long u64;

// ---------------- static device scratch (no allocation allowed) ----------------
__device__ float g_h[2][B_ * H_];            // ping-pong hidden state
__device__ float g_y[B_ * DOUT_];            // previous prediction y_{t-1}
__device__ float g_ypart[16][B_ * DOUT_];    // split-K partials for y projection
__device__ unsigned g_bar_count = 0;         // grid barrier arrival counter
__device__ volatile unsigned g_bar_gen = 0;  // grid barrier generation (monotonic)

// ---------------- packed f32x2 helpers (ptxas will not auto-fuse) --------------
__device__ __forceinline__ u64 ffma2(u64 a, u64 b, u64 c) {
    u64 d;
    asm("fma.rn.f32x2 %0, %1, %2, %3;" : "=l"(d) : "l"(a), "l"(b), "l"(c));
    return d;
}
__device__ __forceinline__ u64 dup2(float x) {
    u64 d;
    asm("mov.b64 %0, {%1, %1};" : "=l"(d) : "f"(x));
    return d;
}
__device__ __forceinline__ float sgm(float v) { return 1.0f / (1.0f + expf(-v)); }

// ---------------- software grid barrier (all 128 CTAs resident) ----------------
__device__ __forceinline__ void gridbar(unsigned target) {
    __syncthreads();
    if (threadIdx.x == 0) {
        __threadfence();
        if (atomicAdd(&g_bar_count, 1u) == NCTA - 1u) {
            g_bar_count = 0u;
            __threadfence();
            g_bar_gen = target;
        } else {
            while ((int)(g_bar_gen - target) < 0) { }
        }
        __threadfence();
    }
    __syncthreads();
}

// ---------------- gate GEMM operand source per K-chunk ----------------
// kg in [0,3072): [0,512)=x_t (Wi rows), [512,1024)=y_prev (Wi rows),
// [1024,3072)=h_prev (Wh rows). Chunk width 32 divides all boundaries.
__device__ __forceinline__ void chunk_src(
    int k0, int t, const float* __restrict__ x, const float* __restrict__ Wi,
    const float* __restrict__ Wh, const float* __restrict__ yprev,
    const float* __restrict__ hprev,
    const float*& Ab, size_t& strA, const float*& Wb)
{
    if (k0 < 512) {
        Ab = x + (size_t)t * DIN_ + (size_t)k0;   // x[m][t][k], row stride T*DIN
        strA = (size_t)T_ * DIN_;
        Wb = Wi + (size_t)k0 * FH_;
    } else if (k0 < 1024) {
        Ab = yprev + (k0 - 512);
        strA = DOUT_;
        Wb = Wi + (size_t)k0 * FH_;
    } else {
        Ab = hprev + (k0 - 1024);
        strA = H_;
        Wb = Wh + (size_t)(k0 - 1024) * FH_;
    }
}

// ---------------- dynamic smem layout (floats) ----------------
// Gates GEMM:
//   Asd(g,buf): dup-packed A, 32 rows x 132 floats (row kk = 64 m dup-pairs)
//   B planes(g,buf,pl): 32 rows x 36 floats each; plane pl holds 16B unit
//     [cols q*8+4*pl .. +3] at [kk][q*4] -> LDS.128 hits 8 distinct 16B banks.
//   z staging aliases the A buffers after the GEMM's final syncthreads.
#define AOFF(g, b)  ((g) * 8448 + (b) * 4224)
#define BOFF(g, b)  (16896 + (g) * 4608 + (b) * 2304)
#define SMEM_FLOATS 26112
#define SMEM_BYTES  (SMEM_FLOATS * 4)

// ======================= single persistent kernel =======================
// 128 CTAs x 512 threads. CTA bx owns hidden units u0=16*bx..u0+15 for all 64
// batch rows: its 64x64 z tile columns are [i|f|g|o] x 16 units (smem col j ->
// weight column (j>>4)*2048 + u0 + (j&15)). Two in-CTA K-groups (warps 0-7:
// K[0,1536); warps 8-15: K[1536,3072)) each run a 2m x 8n per-thread tile and
// their partial z tiles are summed in the fused LSTM epilogue.
__global__ void __launch_bounds__(NTHR, 1) k_lstm_persistent(
    const float* __restrict__ x,  const float* __restrict__ c0,
    const float* __restrict__ h0, const float* __restrict__ y0,
    const float* __restrict__ Wi, const float* __restrict__ Wh,
    const float* __restrict__ bias, const float* __restrict__ Wo,
    const float* __restrict__ bo,
    float* __restrict__ out_c, float* __restrict__ out_h,
    float* __restrict__ out_y, float* __restrict__ out_ys)
{
    extern __shared__ __align__(16) float smB[];

    const int tid = threadIdx.x;
    const int bx  = blockIdx.x;
    const int u0  = bx * 16;

    // ----- gates GEMM mappings (per K-group) -----
    const int g   = tid >> 8;          // K-group 0/1
    const int gt  = tid & 255;
    const int gtx = gt & 7;            // n0 = gtx*8
    const int gty = gt >> 3;           // m0 = gty*2  (32 values)
    const int n0  = gtx * 8;
    // A loader: row am, k-offset ak (two float4s at ak, ak+4)
    const int am = gt & 63;
    const int ak = (gt >> 6) * 8;      // 0,8,16,24
    // B loader: row bk (0..31), column group bq (cols bq*8..bq*8+7)
    const int bk = gt >> 3;
    const int bq = gt & 7;
    const int j0 = bq * 8;
    const int gcol0 = ((j0 >> 4) * 2048) + u0 + (j0 & 15);  // gate-interleaved

    unsigned bar = g_bar_gen;   // persisted base generation (no writers yet)

    // ---------------- init: states ----------------
    {
#pragma unroll
        for (int r = 0; r < 2; r++) {
            int cell = tid + NTHR * r;            // 0..1023
            int mm = cell >> 4, up = cell & 15;
            size_t gi = (size_t)mm * H_ + u0 + up;
            out_c[gi]  = c0[gi];
            g_h[0][gi] = h0[gi];
        }
        if (tid < 256) { int yi = bx * 256 + tid; g_y[yi] = y0[yi]; }
    }
    gridbar(++bar);

    // ---------------- time loop ----------------
    for (int t = 0; t < T_; t++) {
        const int pp = t & 1;
        const float* __restrict__ yprev = g_y;
        const float* __restrict__ hprev = g_h[pp];
        float* __restrict__ hnext       = g_h[pp ^ 1];

        // ===== gates GEMM: per group 48 chunks of K=32, double-buffered =====
        u64 acc[8];
#pragma unroll
        for (int i = 0; i < 8; i++) acc[i] = 0ull;

        {   // preload chunk 0 into buffer 0
            const float *Ab, *Wb; size_t strA;
            chunk_src(g * 1536, t, x, Wi, Wh, yprev, hprev, Ab, strA, Wb);
            float4 a40 = __ldcg((const float4*)(Ab + (size_t)am * strA + ak));
            float4 a41 = __ldcg((const float4*)(Ab + (size_t)am * strA + ak + 4));
            float4 b40 = __ldcg((const float4*)(Wb + (size_t)bk * FH_ + gcol0));
            float4 b41 = __ldcg((const float4*)(Wb + (size_t)bk * FH_ + gcol0 + 4));
            float* Ad = smB + AOFF(g, 0);
            *(float2*)&Ad[(ak + 0) * 132 + am * 2] = make_float2(a40.x, a40.x);
            *(float2*)&Ad[(ak + 1) * 132 + am * 2] = make_float2(a40.y, a40.y);
            *(float2*)&Ad[(ak + 2) * 132 + am * 2] = make_float2(a40.z, a40.z);
            *(float2*)&Ad[(ak + 3) * 132 + am * 2] = make_float2(a40.w, a40.w);
            *(float2*)&Ad[(ak + 4) * 132 + am * 2] = make_float2(a41.x, a41.x);
            *(float2*)&Ad[(ak + 5) * 132 + am * 2] = make_float2(a41.y, a41.y);
            *(float2*)&Ad[(ak + 6) * 132 + am * 2] = make_float2(a41.z, a41.z);
            *(float2*)&Ad[(ak + 7) * 132 + am * 2] = make_float2(a41.w, a41.w);
            float* B0 = smB + BOFF(g, 0);
            *(float4*)&B0[bk * 36 + bq * 4]        = b40;
            *(float4*)&B0[1152 + bk * 36 + bq * 4] = b41;
        }
        __syncthreads();

        for (int c = 0; c < 48; c++) {
            const int cur = c & 1;
            const bool hn = (c + 1 < 48);
            float4 a40, a41, b40, b41;
            if (hn) {
                const float *Ab, *Wb; size_t strA;
                chunk_src(g * 1536 + (c + 1) * 32, t, x, Wi, Wh, yprev, hprev,
                          Ab, strA, Wb);
                a40 = __ldcg((const float4*)(Ab + (size_t)am * strA + ak));
                a41 = __ldcg((const float4*)(Ab + (size_t)am * strA + ak + 4));
                b40 = __ldcg((const float4*)(Wb + (size_t)bk * FH_ + gcol0));
                b41 = __ldcg((const float4*)(Wb + (size_t)bk * FH_ + gcol0 + 4));
            }

            const float* Ad = smB + AOFF(g, cur);
            const float* B0 = smB + BOFF(g, cur);
            const float* B1 = B0 + 1152;
#pragma unroll 16
            for (int kk = 0; kk < 32; kk++) {
                ulonglong2 aa = *(const ulonglong2*)&Ad[kk * 132 + gty * 4]; // {dup m0, dup m0+1}
                ulonglong2 bA = *(const ulonglong2*)&B0[kk * 36 + gtx * 4];  // pairs n0..n0+3
                ulonglong2 bB = *(const ulonglong2*)&B1[kk * 36 + gtx * 4];  // pairs n0+4..n0+7
                acc[0] = ffma2(aa.x, bA.x, acc[0]);
                acc[1] = ffma2(aa.x, bA.y, acc[1]);
                acc[2] = ffma2(aa.x, bB.x, acc[2]);
                acc[3] = ffma2(aa.x, bB.y, acc[3]);
                acc[4] = ffma2(aa.y, bA.x, acc[4]);
                acc[5] = ffma2(aa.y, bA.y, acc[5]);
                acc[6] = ffma2(aa.y, bB.x, acc[6]);
                acc[7] = ffma2(aa.y, bB.y, acc[7]);
            }

            if (hn) {
                const int nb2 = cur ^ 1;
                float* Ad2 = smB + AOFF(g, nb2);
                *(float2*)&Ad2[(ak + 0) * 132 + am * 2] = make_float2(a40.x, a40.x);
                *(float2*)&Ad2[(ak + 1) * 132 + am * 2] = make_float2(a40.y, a40.y);
                *(float2*)&Ad2[(ak + 2) * 132 + am * 2] = make_float2(a40.z, a40.z);
                *(float2*)&Ad2[(ak + 3) * 132 + am * 2] = make_float2(a40.w, a40.w);
                *(float2*)&Ad2[(ak + 4) * 132 + am * 2] = make_float2(a41.x, a41.x);
                *(float2*)&Ad2[(ak + 5) * 132 + am * 2] = make_float2(a41.y, a41.y);
                *(float2*)&Ad2[(ak + 6) * 132 + am * 2] = make_float2(a41.z, a41.z);
                *(float2*)&Ad2[(ak + 7) * 132 + am * 2] = make_float2(a41.w, a41.w);
                float* B0w = smB + BOFF(g, nb2);
                *(float4*)&B0w[bk * 36 + bq * 4]        = b40;
                *(float4*)&B0w[1152 + bk * 36 + bq * 4] = b41;
            }
            __syncthreads();
        }

        // ===== stage both groups' z partials; fused LSTM pointwise =====
        {
            float* zz = smB + g * 4352;   // z_g[m][68], aliases A buffers (post-sync)
            const int m0 = gty * 2;
            *(u64*)&zz[(m0 + 0) * 68 + n0]     = acc[0];
            *(u64*)&zz[(m0 + 0) * 68 + n0 + 2] = acc[1];
            *(u64*)&zz[(m0 + 0) * 68 + n0 + 4] = acc[2];
            *(u64*)&zz[(m0 + 0) * 68 + n0 + 6] = acc[3];
            *(u64*)&zz[(m0 + 1) * 68 + n0]     = acc[4];
            *(u64*)&zz[(m0 + 1) * 68 + n0 + 2] = acc[5];
            *(u64*)&zz[(m0 + 1) * 68 + n0 + 4] = acc[6];
            *(u64*)&zz[(m0 + 1) * 68 + n0 + 6] = acc[7];
            __syncthreads();
#pragma unroll
            for (int r = 0; r < 2; r++) {
                int cell = tid + NTHR * r;        // 0..1023
                int mm = cell >> 4, up = cell & 15;
                float zi = smB[mm * 68 + up]        + smB[4352 + mm * 68 + up]
                         + bias[u0 + up];
                float zf = smB[mm * 68 + 16 + up]   + smB[4352 + mm * 68 + 16 + up]
                         + bias[2048 + u0 + up];
                float zg = smB[mm * 68 + 32 + up]   + smB[4352 + mm * 68 + 32 + up]
                         + bias[4096 + u0 + up];
                float zo = smB[mm * 68 + 48 + up]   + smB[4352 + mm * 68 + 48 + up]
                         + bias[6144 + u0 + up];
                size_t gi = (size_t)mm * H_ + u0 + up;
                float cold = out_c[gi];            // CTA-private: L1-resident
                float nc = sgm(zf) * cold + sgm(zi) * tanhf(zg);
                float nh = sgm(zo) * tanhf(nc);
                out_c[gi] = nc;
                hnext[gi] = nh;
            }
        }
        gridbar(++bar);   // h_t published

        // ===== y projection: split K(16 x 128) x N(8 x 64) =====
        {
            const int nb = bx & 7, ks = bx >> 3;
            const int kbase = ks * 128;
            const float* __restrict__ h = g_h[pp ^ 1];
            const int ytx = tid & 15, yty = tid >> 4;      // n=ytx*4, m=yty*2
            const int yam = tid & 63, yak = (tid >> 6) * 4;
            const int ybk = tid >> 4, ybc = (tid & 15) * 4;
            u64 ya[4] = {0ull, 0ull, 0ull, 0ull};
            for (int c = 0; c < 4; c++) {
                int k0 = kbase + c * 32;
                float4 a4 = __ldcg((const float4*)(h + (size_t)yam * H_ + k0 + yak));
                float4 b4 = __ldcg((const float4*)(Wo + (size_t)(k0 + ybk) * DOUT_ + nb * 64 + ybc));
                __syncthreads();
                smB[(yak + 0) * 68 + yam] = a4.x;
                smB[(yak + 1) * 68 + yam] = a4.y;
                smB[(yak + 2) * 68 + yam] = a4.z;
                smB[(yak + 3) * 68 + yam] = a4.w;
                *(float4*)&smB[4352 + ybk * 68 + ybc] = b4;
                __syncthreads();
#pragma unroll 16
                for (int kk = 0; kk < 32; kk++) {
                    float2 av = *(const float2*)&smB[kk * 68 + yty * 2];
                    ulonglong2 bv = *(const ulonglong2*)&smB[4352 + kk * 68 + ytx * 4];
                    u64 a0 = dup2(av.x), a1 = dup2(av.y);
                    ya[0] = ffma2(a0, bv.x, ya[0]);
                    ya[1] = ffma2(a0, bv.y, ya[1]);
                    ya[2] = ffma2(a1, bv.x, ya[2]);
                    ya[3] = ffma2(a1, bv.y, ya[3]);
                }
            }
            float* d0 = &g_ypart[ks][(size_t)(yty * 2 + 0) * DOUT_ + nb * 64 + ytx * 4];
            float* d1 = &g_ypart[ks][(size_t)(yty * 2 + 1) * DOUT_ + nb * 64 + ytx * 4];
            *(u64*)d0 = ya[0]; *(u64*)(d0 + 2) = ya[1];
            *(u64*)d1 = ya[2]; *(u64*)(d1 + 2) = ya[3];
        }
        gridbar(++bar);   // partials published

        // ===== y reduce: 256 outputs per CTA =====
        if (tid < 256) {
            int o = bx * 256 + tid;               // 0..32767
            float s = __ldg(&bo[o & 511]);
#pragma unroll
            for (int ks = 0; ks < 16; ks++) s += __ldcg(&g_ypart[ks][o]);
            g_y[o] = s;
            int mm = o >> 9, cN = o & 511;
            out_ys[(size_t)mm * ((size_t)T_ * DOUT_) + (size_t)t * DOUT_ + cN] = s;
        }
        gridbar(++bar);   // y_t published
    }

    // ---------------- final: h_f, y_f ----------------
    {
        int idx = bx * NTHR + tid;                // 0..65535
        out_h[idx]         = __ldcg(&g_h[0][idx]);   // T even -> final h in buf 0
        out_h[idx + 65536] = __ldcg(&g_h[0][idx + 65536]);
        if (idx < B_ * DOUT_) out_y[idx] = __ldcg(&g_y[idx]);
    }
}

// ---------------- host launcher: ONE graph node ----------------
extern "C" void kernel_launch(void* const* d_in, const int* in_sizes, int n_in,
                              void* d_out, int out_size) {
    (void)in_sizes; (void)n_in; (void)out_size;
    const float* x  = (const float*)d_in[0];
    const float* c0 = (const float*)d_in[1];
    const float* h0 = (const float*)d_in[2];
    const float* y0 = (const float*)d_in[3];
    const float* Wi = (const float*)d_in[4];
    const float* Wh = (const float*)d_in[5];
    const float* b  = (const float*)d_in[6];
    const float* Wo = (const float*)d_in[7];
    const float* bo = (const float*)d_in[8];

    // Output layout: c_f [64,2048] | h_f [64,2048] | y_f [64,512] | ys [64,1024,512]
    float* out    = (float*)d_out;
    float* out_c  = out;
    float* out_h  = out + 131072;
    float* out_y  = out + 262144;
    float* out_ys = out + 294912;

    cudaFuncSetAttribute(k_lstm_persistent,
                         cudaFuncAttributeMaxDynamicSharedMemorySize, SMEM_BYTES);
    k_lstm_persistent<<<NCTA, NTHR, SMEM_BYTES>>>(x, c0, h0, y0, Wi, Wh, b, Wo, bo,
                                                  out_c, out_h, out_y, out_ys);
}